// round 2
// baseline (speedup 1.0000x reference)
#include <cuda_runtime.h>
#include <cuda_bf16.h>

// Problem constants (fixed by the reference)
#define B_   2
#define S_   2048
#define D_   1024
#define H_   16
#define DH_  64
#define N_   (B_ * S_)   // 4096 tokens

// ---------------------------------------------------------------------------
// Scratch (device globals — no allocation allowed)
// ---------------------------------------------------------------------------
__device__ float g_q[B_ * H_ * S_ * DH_];   // [b][h][s][dh]
__device__ float g_k[B_ * H_ * S_ * DH_];
__device__ float g_v[B_ * H_ * S_ * DH_];
__device__ float g_att[N_ * D_];            // [n][h*64+dh]

// ---------------------------------------------------------------------------
// TN GEMM with bias: C[n,o] = sum_k A[n,k] * W[o,k] + bias[o]
// A: [N,K] row-major, W: [O,K] row-major (both K-contiguous).
// scatter==1: write to head-major layout [b][h][s][dh] (for Q/K/V)
// scatter==0: write row-major [n][o]
// Tiles: 64x64, BK=16, 256 threads, 4x4 microtile.
// ---------------------------------------------------------------------------
#define GP 68   // padded row stride (floats) for transposed smem tiles

__global__ void __launch_bounds__(256)
gemm_tn_bias(const float* __restrict__ A, const float* __restrict__ W,
             const float* __restrict__ bias, float* __restrict__ C,
             int K, int O, int scatter)
{
    __shared__ float Ast[16][GP];   // [k][n-row]
    __shared__ float Wst[16][GP];   // [k][o-col]

    const int bn = blockIdx.x;   // o-block
    const int bm = blockIdx.y;   // n-block
    const int t  = threadIdx.x;
    const int tx = t & 15;
    const int ty = t >> 4;

    const int lrow = t >> 2;          // 0..63
    const int lk   = (t & 3) * 4;     // 0,4,8,12

    const float* Ap = A + (size_t)(bm * 64 + lrow) * K + lk;
    const float* Wp = W + (size_t)(bn * 64 + lrow) * K + lk;

    float acc[4][4];
#pragma unroll
    for (int i = 0; i < 4; i++)
#pragma unroll
        for (int j = 0; j < 4; j++) acc[i][j] = 0.f;

    for (int k0 = 0; k0 < K; k0 += 16) {
        float4 a4 = *(const float4*)(Ap + k0);
        float4 w4 = *(const float4*)(Wp + k0);
        __syncthreads();
        Ast[lk + 0][lrow] = a4.x; Ast[lk + 1][lrow] = a4.y;
        Ast[lk + 2][lrow] = a4.z; Ast[lk + 3][lrow] = a4.w;
        Wst[lk + 0][lrow] = w4.x; Wst[lk + 1][lrow] = w4.y;
        Wst[lk + 2][lrow] = w4.z; Wst[lk + 3][lrow] = w4.w;
        __syncthreads();
#pragma unroll
        for (int kk = 0; kk < 16; kk++) {
            float4 av = *(const float4*)&Ast[kk][ty << 2];
            float4 wv = *(const float4*)&Wst[kk][tx << 2];
            acc[0][0] += av.x * wv.x; acc[0][1] += av.x * wv.y;
            acc[0][2] += av.x * wv.z; acc[0][3] += av.x * wv.w;
            acc[1][0] += av.y * wv.x; acc[1][1] += av.y * wv.y;
            acc[1][2] += av.y * wv.z; acc[1][3] += av.y * wv.w;
            acc[2][0] += av.z * wv.x; acc[2][1] += av.z * wv.y;
            acc[2][2] += av.z * wv.z; acc[2][3] += av.z * wv.w;
            acc[3][0] += av.w * wv.x; acc[3][1] += av.w * wv.y;
            acc[3][2] += av.w * wv.z; acc[3][3] += av.w * wv.w;
        }
    }

    const int n0 = bm * 64 + (ty << 2);
    const int o0 = bn * 64 + (tx << 2);
#pragma unroll
    for (int i = 0; i < 4; i++) {
        const int n = n0 + i;
#pragma unroll
        for (int j = 0; j < 4; j++) {
            const int o = o0 + j;
            const float val = acc[i][j] + bias[o];
            if (scatter) {
                const int b  = n >> 11;           // n / S_
                const int s  = n & (S_ - 1);
                const int h  = o >> 6;
                const int dh = o & 63;
                C[(((size_t)(b * H_ + h)) * S_ + s) * DH_ + dh] = val;
            } else {
                C[(size_t)n * O + o] = val;
            }
        }
    }
}

// ---------------------------------------------------------------------------
// Flash attention: one CTA handles 64 query rows of one (b,h).
// Loops over 32 K/V blocks of 64 keys. Online softmax in registers.
// smem: Qt[64][68] (dh-major), Kt[64][68] (dh-major), Vs[64][68], Ps[64][68]
// ---------------------------------------------------------------------------
#define FP 68

__global__ void __launch_bounds__(256)
flash_kernel(const int* __restrict__ mask, float* __restrict__ out)
{
    extern __shared__ float sm[];
    float* Qt = sm;                 // [dh][row]  64*FP
    float* Kt = Qt + 64 * FP;       // [dh][col]
    float* Vs = Kt + 64 * FP;       // [row][dh]
    float* Ps = Vs + 64 * FP;       // [row][col]
    int*  msk = (int*)(Ps + 64 * FP);

    const int qb = blockIdx.x;
    const int h  = blockIdx.y;
    const int b  = blockIdx.z;

    const float* Qg = g_q + ((size_t)(b * H_ + h)) * S_ * DH_;
    const float* Kg = g_k + ((size_t)(b * H_ + h)) * S_ * DH_;
    const float* Vg = g_v + ((size_t)(b * H_ + h)) * S_ * DH_;

    const int t  = threadIdx.x;
    const int tx = t & 15;
    const int ty = t >> 4;
    const int lrow = t >> 2;          // 0..63
    const int lq   = t & 3;           // float4 phase

    // Load Q tile transposed: Qt[dh][row]
#pragma unroll
    for (int i = 0; i < 4; i++) {
        const int dh0 = 4 * (lq + 4 * i);
        float4 q4 = *(const float4*)(Qg + (size_t)(qb * 64 + lrow) * DH_ + dh0);
        Qt[(dh0 + 0) * FP + lrow] = q4.x;
        Qt[(dh0 + 1) * FP + lrow] = q4.y;
        Qt[(dh0 + 2) * FP + lrow] = q4.z;
        Qt[(dh0 + 3) * FP + lrow] = q4.w;
    }

    float m_i[4], l_i[4], o_acc[4][4];
#pragma unroll
    for (int i = 0; i < 4; i++) {
        m_i[i] = -1e30f; l_i[i] = 0.f;
#pragma unroll
        for (int j = 0; j < 4; j++) o_acc[i][j] = 0.f;
    }

    for (int kb = 0; kb < S_ / 64; kb++) {
        __syncthreads();   // previous P@V done; Qt visible on first iter
        // Load K tile transposed, V tile direct, mask slice
#pragma unroll
        for (int i = 0; i < 4; i++) {
            const int dh0 = 4 * (lq + 4 * i);
            float4 k4 = *(const float4*)(Kg + (size_t)(kb * 64 + lrow) * DH_ + dh0);
            Kt[(dh0 + 0) * FP + lrow] = k4.x;
            Kt[(dh0 + 1) * FP + lrow] = k4.y;
            Kt[(dh0 + 2) * FP + lrow] = k4.z;
            Kt[(dh0 + 3) * FP + lrow] = k4.w;
            float4 v4 = *(const float4*)(Vg + (size_t)(kb * 64 + lrow) * DH_ + dh0);
            *(float4*)&Vs[lrow * FP + dh0] = v4;
        }
        if (t < 64) msk[t] = mask[b * S_ + kb * 64 + t];
        __syncthreads();

        // Scores: s[i][j] = sum_dh Qt[dh][4ty+i] * Kt[dh][4tx+j]
        float s[4][4];
#pragma unroll
        for (int i = 0; i < 4; i++)
#pragma unroll
            for (int j = 0; j < 4; j++) s[i][j] = 0.f;
#pragma unroll 8
        for (int kk = 0; kk < 64; kk++) {
            float4 qv = *(const float4*)&Qt[kk * FP + (ty << 2)];
            float4 kv = *(const float4*)&Kt[kk * FP + (tx << 2)];
            s[0][0] += qv.x * kv.x; s[0][1] += qv.x * kv.y;
            s[0][2] += qv.x * kv.z; s[0][3] += qv.x * kv.w;
            s[1][0] += qv.y * kv.x; s[1][1] += qv.y * kv.y;
            s[1][2] += qv.y * kv.z; s[1][3] += qv.y * kv.w;
            s[2][0] += qv.z * kv.x; s[2][1] += qv.z * kv.y;
            s[2][2] += qv.z * kv.z; s[2][3] += qv.z * kv.w;
            s[3][0] += qv.w * kv.x; s[3][1] += qv.w * kv.y;
            s[3][2] += qv.w * kv.z; s[3][3] += qv.w * kv.w;
        }

        // Scale + mask
#pragma unroll
        for (int j = 0; j < 4; j++) {
            const bool ok = msk[(tx << 2) + j] != 0;
#pragma unroll
            for (int i = 0; i < 4; i++)
                s[i][j] = ok ? s[i][j] * 0.125f : -1e9f;
        }

        // Online softmax (row stats across the 16 tx lanes)
#pragma unroll
        for (int i = 0; i < 4; i++) {
            float rmax = fmaxf(fmaxf(s[i][0], s[i][1]), fmaxf(s[i][2], s[i][3]));
#pragma unroll
            for (int d = 1; d <= 8; d <<= 1)
                rmax = fmaxf(rmax, __shfl_xor_sync(0xffffffffu, rmax, d));
            const float mnew  = fmaxf(m_i[i], rmax);
            const float alpha = __expf(m_i[i] - mnew);
            float rsum = 0.f;
#pragma unroll
            for (int j = 0; j < 4; j++) {
                s[i][j] = __expf(s[i][j] - mnew);
                rsum += s[i][j];
            }
#pragma unroll
            for (int d = 1; d <= 8; d <<= 1)
                rsum += __shfl_xor_sync(0xffffffffu, rsum, d);
            l_i[i] = l_i[i] * alpha + rsum;
            m_i[i] = mnew;
#pragma unroll
            for (int j = 0; j < 4; j++) o_acc[i][j] *= alpha;
            // stash P row chunk
            *(float4*)&Ps[((ty << 2) + i) * FP + (tx << 2)] =
                make_float4(s[i][0], s[i][1], s[i][2], s[i][3]);
        }
        __syncthreads();

        // O += P @ V
#pragma unroll 8
        for (int jj = 0; jj < 64; jj++) {
            const float4 vv = *(const float4*)&Vs[jj * FP + (tx << 2)];
            const float p0 = Ps[((ty << 2) + 0) * FP + jj];
            const float p1 = Ps[((ty << 2) + 1) * FP + jj];
            const float p2 = Ps[((ty << 2) + 2) * FP + jj];
            const float p3 = Ps[((ty << 2) + 3) * FP + jj];
            o_acc[0][0] += p0 * vv.x; o_acc[0][1] += p0 * vv.y;
            o_acc[0][2] += p0 * vv.z; o_acc[0][3] += p0 * vv.w;
            o_acc[1][0] += p1 * vv.x; o_acc[1][1] += p1 * vv.y;
            o_acc[1][2] += p1 * vv.z; o_acc[1][3] += p1 * vv.w;
            o_acc[2][0] += p2 * vv.x; o_acc[2][1] += p2 * vv.y;
            o_acc[2][2] += p2 * vv.z; o_acc[2][3] += p2 * vv.w;
            o_acc[3][0] += p3 * vv.x; o_acc[3][1] += p3 * vv.y;
            o_acc[3][2] += p3 * vv.z; o_acc[3][3] += p3 * vv.w;
        }
    }

    // Epilogue: normalize and write to [n][h*64+dh] layout
#pragma unroll
    for (int i = 0; i < 4; i++) {
        const float inv = 1.f / l_i[i];
        const int sg = qb * 64 + (ty << 2) + i;
#pragma unroll
        for (int j = 0; j < 4; j++) {
            out[((size_t)(b * S_ + sg)) * D_ + h * DH_ + (tx << 2) + j] =
                o_acc[i][j] * inv;
        }
    }
}

// ---------------------------------------------------------------------------
// Launch
// ---------------------------------------------------------------------------
extern "C" void kernel_launch(void* const* d_in, const int* in_sizes, int n_in,
                              void* d_out, int out_size)
{
    (void)in_sizes; (void)n_in; (void)out_size;
    const float* x    = (const float*)d_in[0];
    const int*   mask = (const int*)  d_in[1];
    const float* Wq   = (const float*)d_in[2];
    const float* bq   = (const float*)d_in[3];
    const float* Wk   = (const float*)d_in[4];
    const float* bk   = (const float*)d_in[5];
    const float* Wv   = (const float*)d_in[6];
    const float* bv   = (const float*)d_in[7];
    const float* Wo   = (const float*)d_in[8];
    const float* bo   = (const float*)d_in[9];
    float* out = (float*)d_out;

    float *qp, *kp, *vp, *ap;
    cudaGetSymbolAddress((void**)&qp, g_q);
    cudaGetSymbolAddress((void**)&kp, g_k);
    cudaGetSymbolAddress((void**)&vp, g_v);
    cudaGetSymbolAddress((void**)&ap, g_att);

    const int flash_smem = (4 * 64 * FP) * 4 + 64 * 4;  // 69888 bytes
    cudaFuncSetAttribute(flash_kernel,
                         cudaFuncAttributeMaxDynamicSharedMemorySize, flash_smem);

    dim3 gg(D_ / 64, N_ / 64);   // (16, 64)
    gemm_tn_bias<<<gg, 256>>>(x, Wq, bq, qp, D_, D_, 1);
    gemm_tn_bias<<<gg, 256>>>(x, Wk, bk, kp, D_, D_, 1);
    gemm_tn_bias<<<gg, 256>>>(x, Wv, bv, vp, D_, D_, 1);

    flash_kernel<<<dim3(S_ / 64, H_, B_), 256, flash_smem>>>(mask, ap);

    gemm_tn_bias<<<gg, 256>>>(ap, Wo, bo, out, D_, D_, 0);
}